// round 12
// baseline (speedup 1.0000x reference)
#include <cuda_runtime.h>
#include <cuda_fp16.h>
#include <cstdint>

// ---------------------------------------------------------------------------
// DSQGAttention, fp16 mma.sync path.
// qkv = x @ w_qkv ; gather-attn (44 offsets) ; out = attn @ w_out
// R10: attention stages k/v/(1+se) in fp16 (half the smem traffic), math fp32.
// ---------------------------------------------------------------------------

#define T_DIM 2048
#define C_DIM 1024
#define H_DIM 16
#define J_DIM 44
#define QKV_N 3072
#define K_DIM 1024

__device__ float g_qkv[T_DIM * QKV_N];     // fp32 qkv
__device__ __half g_attn[T_DIM * C_DIM];   // attention out (fp16 for GEMM2)
__device__ __half g_xh[T_DIM * C_DIM];     // x, fp16
__device__ __half g_wqt[QKV_N * K_DIM];    // w_qkv^T, fp16  [n][k]
__device__ __half g_wot[C_DIM * K_DIM];    // w_out^T, fp16  [n][k]

__constant__ int c_deltas[J_DIM] = {
    0,1,2,3,4,5,6,7,8,9,10,11,12,13,14,15,16,17,18,19,
    20,21,22,23,24,25,26,27,28,29,30,31,32,33,34,35,36,37,38,39,
    40,128,384,1536
};

__device__ __forceinline__ uint32_t smem_u32(const void* p) {
    uint32_t a;
    asm("{ .reg .u64 t; cvta.to.shared.u64 t, %1; cvt.u32.u64 %0, t; }"
        : "=r"(a) : "l"(p));
    return a;
}
__device__ __forceinline__ void cp16(uint32_t s, const void* g) {
    asm volatile("cp.async.cg.shared.global [%0], [%1], 16;" :: "r"(s), "l"(g));
}
#define CP_COMMIT() asm volatile("cp.async.commit_group;" ::: "memory")
#define CP_WAIT1()  asm volatile("cp.async.wait_group 1;" ::: "memory")

__device__ __forceinline__ void ldsm_x4(uint32_t& r0, uint32_t& r1,
                                        uint32_t& r2, uint32_t& r3, uint32_t a) {
    asm volatile("ldmatrix.sync.aligned.m8n8.x4.shared.b16 {%0,%1,%2,%3}, [%4];"
                 : "=r"(r0), "=r"(r1), "=r"(r2), "=r"(r3) : "r"(a));
}
#define MMA_F16(acc, af, b0, b1)                                               \
    asm volatile(                                                              \
        "mma.sync.aligned.m16n8k16.row.col.f32.f16.f16.f32 "                   \
        "{%0,%1,%2,%3}, {%4,%5,%6,%7}, {%8,%9}, {%0,%1,%2,%3};"                \
        : "+f"((acc)[0]), "+f"((acc)[1]), "+f"((acc)[2]), "+f"((acc)[3])       \
        : "r"((af)[0]), "r"((af)[1]), "r"((af)[2]), "r"((af)[3]),              \
          "r"(b0), "r"(b1))

__device__ __forceinline__ float4 h4_to_f4(uint2 raw) {
    float2 a = __half22float2(*reinterpret_cast<__half2*>(&raw.x));
    float2 b = __half22float2(*reinterpret_cast<__half2*>(&raw.y));
    return make_float4(a.x, a.y, b.x, b.y);
}
__device__ __forceinline__ uint2 f4_to_h4(float4 v) {
    __half2 h0 = __floats2half2_rn(v.x, v.y);
    __half2 h1 = __floats2half2_rn(v.z, v.w);
    uint2 o;
    o.x = *reinterpret_cast<unsigned*>(&h0);
    o.y = *reinterpret_cast<unsigned*>(&h1);
    return o;
}

// ---------------------------------------------------------------------------
// Pre-pass: fp32 -> fp16 (same layout)
// ---------------------------------------------------------------------------
__global__ void roundh_kernel(const float* __restrict__ src,
                              __half* __restrict__ dst, int n4)
{
    int i = blockIdx.x * blockDim.x + threadIdx.x;
    if (i >= n4) return;
    ((uint2*)dst)[i] = f4_to_h4(((const float4*)src)[i]);
}

// ---------------------------------------------------------------------------
// Pre-pass: both weight transposes (z=0: w_qkv, z=1: w_out), fp16 output
// ---------------------------------------------------------------------------
__global__ void tround2_kernel(const float* __restrict__ wq, __half* __restrict__ wqt,
                               const float* __restrict__ wo, __half* __restrict__ wot)
{
    __shared__ float tile[32][33];
    const int z = blockIdx.z;
    const float* src = z ? wo : wq;
    __half* dst = z ? wot : wqt;
    const int Cc = z ? C_DIM : QKV_N;
    int bx = blockIdx.x, by = blockIdx.y;
    if (bx * 32 >= Cc) return;
    int tx = threadIdx.x, ty = threadIdx.y;
#pragma unroll
    for (int i = 0; i < 4; i++)
        tile[ty + 8*i][tx] = src[(size_t)(by*32 + ty + 8*i) * Cc + bx*32 + tx];
    __syncthreads();
#pragma unroll
    for (int i = 0; i < 4; i++)
        dst[(size_t)(bx*32 + ty + 8*i) * K_DIM + by*32 + tx] =
            __float2half_rn(tile[tx][ty + 8*i]);
}

// ---------------------------------------------------------------------------
// GEMM1: 128x128 tile, BK=64 fp16, 3-stage, 8 warps (2m x 4n), wtile 64x32.
// ---------------------------------------------------------------------------
#define GEMM_SMEM_128 (3 * 32768)
#define N_CHUNK (K_DIM / 64)   // 16

__global__ __launch_bounds__(256, 2)
void h_gemm128(const __half* __restrict__ A, const __half* __restrict__ B,
               float* __restrict__ C, int M, int N)
{
    extern __shared__ __align__(1024) char dyn_smem[];
    const uint32_t dsm = smem_u32(dyn_smem);

    const int tid  = threadIdx.x;
    const int wid  = tid >> 5;
    const int lane = tid & 31;
    const int bm = blockIdx.y * 128;
    const int bn = blockIdx.x * 128;
    const int wm = (wid & 1) * 64;
    const int wn = (wid >> 1) * 32;
    const int g   = lane >> 2;
    const int tig = lane & 3;

    const int ld_row = tid >> 1;
    const int ld_s0  = (tid & 1) * 4;
    const __half* gA = A + (size_t)(bm + ld_row) * K_DIM + ld_s0 * 8;
    const __half* gB = B + (size_t)(bn + ld_row) * K_DIM + ld_s0 * 8;
    const int ld_swz = (ld_row & 7) << 4;
    const uint32_t sA_row = ld_row * 128;

    const int swz   = (lane & 7) << 4;
    const int a_row = wm + (((lane >> 3) & 1) << 3) + (lane & 7);
    const int a_s16 = (lane >> 4) << 4;
    const int b_s16 = ((lane >> 3) & 1) << 4;
    const int b_rw  = wn + ((lane >> 4) << 3) + (lane & 7);

    float acc[4][4][4];
#pragma unroll
    for (int mt = 0; mt < 4; mt++)
#pragma unroll
        for (int nt = 0; nt < 4; nt++)
#pragma unroll
            for (int r = 0; r < 4; r++) acc[mt][nt][r] = 0.0f;

#define ISSUE_CHUNK1(c, buf)                                                   \
    do {                                                                       \
        const uint32_t sb = dsm + (buf) * 32768;                               \
        const int kf = (c) * 64;                                               \
        _Pragma("unroll")                                                      \
        for (int i = 0; i < 4; i++) {                                          \
            const int sg = ld_s0 + i;                                          \
            const uint32_t so = sA_row + ((sg * 16) ^ ld_swz);                 \
            cp16(sb + so,         gA + kf + i * 8);                            \
            cp16(sb + 16384 + so, gB + kf + i * 8);                            \
        }                                                                      \
    } while (0)

    ISSUE_CHUNK1(0, 0); CP_COMMIT();
    ISSUE_CHUNK1(1, 1); CP_COMMIT();

    for (int c = 0; c < N_CHUNK; c++) {
        CP_WAIT1();
        __syncthreads();

        const int buf = c % 3;
        const uint32_t aB = dsm + buf * 32768;
        const uint32_t bB = aB + 16384;
        const uint32_t a_base = aB + a_row * 128;
        const uint32_t b_base = bB + b_rw * 128;

#pragma unroll
        for (int kk = 0; kk < 4; kk++) {
            uint32_t af[4][4], bf[4][2];
            const uint32_t kbA = (uint32_t)((kk * 32 + a_s16) ^ swz);
            const uint32_t kbB = (uint32_t)((kk * 32 + b_s16) ^ swz);
#pragma unroll
            for (int mt = 0; mt < 4; mt++)
                ldsm_x4(af[mt][0], af[mt][1], af[mt][2], af[mt][3],
                        a_base + mt * 2048 + kbA);
#pragma unroll
            for (int p = 0; p < 2; p++)
                ldsm_x4(bf[2*p][0], bf[2*p][1], bf[2*p+1][0], bf[2*p+1][1],
                        b_base + p * 2048 + kbB);
#pragma unroll
            for (int mt = 0; mt < 4; mt++)
#pragma unroll
                for (int nt = 0; nt < 4; nt++)
                    MMA_F16(acc[mt][nt], af[mt], bf[nt][0], bf[nt][1]);
        }

        if (c + 2 < N_CHUNK) ISSUE_CHUNK1(c + 2, (c + 2) % 3);
        CP_COMMIT();
    }
#undef ISSUE_CHUNK1

#pragma unroll
    for (int mt = 0; mt < 4; mt++) {
#pragma unroll
        for (int nt = 0; nt < 4; nt++) {
            int row = bm + wm + mt * 16 + g;
            int col = bn + wn + nt * 8 + tig * 2;
            *(float2*)&C[(size_t)row * N + col] =
                make_float2(acc[mt][nt][0], acc[mt][nt][1]);
            *(float2*)&C[(size_t)(row + 8) * N + col] =
                make_float2(acc[mt][nt][2], acc[mt][nt][3]);
        }
    }
}

// ---------------------------------------------------------------------------
// GEMM2: 64x128 tile, BK=64 fp16, 3-stage, 3 CTA/SM. Grid 256 -> 1 wave.
// ---------------------------------------------------------------------------
#define GEMM_SMEM_64 (3 * 24576)

__global__ __launch_bounds__(256, 3)
void h_gemm64(const __half* __restrict__ A, const __half* __restrict__ B,
              float* __restrict__ C, int M, int N)
{
    extern __shared__ __align__(1024) char dyn_smem[];
    const uint32_t dsm = smem_u32(dyn_smem);

    const int tid  = threadIdx.x;
    const int wid  = tid >> 5;
    const int lane = tid & 31;
    const int bm = blockIdx.y * 64;
    const int bn = blockIdx.x * 128;
    const int wm = (wid & 1) * 32;
    const int wn = (wid >> 1) * 32;
    const int g   = lane >> 2;
    const int tig = lane & 3;

    const int a_ld_row = tid >> 2;
    const int a_ld_s0  = (tid & 3) * 2;
    const int b_ld_row = tid >> 1;
    const int b_ld_s0  = (tid & 1) * 4;

    const __half* gA = A + (size_t)(bm + a_ld_row) * K_DIM + a_ld_s0 * 8;
    const __half* gB = B + (size_t)(bn + b_ld_row) * K_DIM + b_ld_s0 * 8;
    const int a_swz = (a_ld_row & 7) << 4;
    const int b_swz = (b_ld_row & 7) << 4;
    const uint32_t a_srow = a_ld_row * 128;
    const uint32_t b_srow = b_ld_row * 128;

    const int swz   = (lane & 7) << 4;
    const int a_row = wm + (((lane >> 3) & 1) << 3) + (lane & 7);
    const int a_s16 = (lane >> 4) << 4;
    const int b_s16 = ((lane >> 3) & 1) << 4;
    const int b_rw  = wn + ((lane >> 4) << 3) + (lane & 7);

    float acc[2][4][4];
#pragma unroll
    for (int mt = 0; mt < 2; mt++)
#pragma unroll
        for (int nt = 0; nt < 4; nt++)
#pragma unroll
            for (int r = 0; r < 4; r++) acc[mt][nt][r] = 0.0f;

#define ISSUE_CHUNK2(c, buf)                                                   \
    do {                                                                       \
        const uint32_t sb = dsm + (buf) * 24576;                               \
        const int kf = (c) * 64;                                               \
        _Pragma("unroll")                                                      \
        for (int i = 0; i < 2; i++) {                                          \
            const uint32_t so = a_srow + (((a_ld_s0 + i) * 16) ^ a_swz);       \
            cp16(sb + so, gA + kf + i * 8);                                    \
        }                                                                      \
        _Pragma("unroll")                                                      \
        for (int i = 0; i < 4; i++) {                                          \
            const uint32_t so = b_srow + (((b_ld_s0 + i) * 16) ^ b_swz);       \
            cp16(sb + 8192 + so, gB + kf + i * 8);                             \
        }                                                                      \
    } while (0)

    ISSUE_CHUNK2(0, 0); CP_COMMIT();
    ISSUE_CHUNK2(1, 1); CP_COMMIT();

    for (int c = 0; c < N_CHUNK; c++) {
        CP_WAIT1();
        __syncthreads();

        const int buf = c % 3;
        const uint32_t aB = dsm + buf * 24576;
        const uint32_t bB = aB + 8192;
        const uint32_t a_base = aB + a_row * 128;
        const uint32_t b_base = bB + b_rw * 128;

#pragma unroll
        for (int kk = 0; kk < 4; kk++) {
            uint32_t af[2][4], bf[4][2];
            const uint32_t kbA = (uint32_t)((kk * 32 + a_s16) ^ swz);
            const uint32_t kbB = (uint32_t)((kk * 32 + b_s16) ^ swz);
#pragma unroll
            for (int mt = 0; mt < 2; mt++)
                ldsm_x4(af[mt][0], af[mt][1], af[mt][2], af[mt][3],
                        a_base + mt * 2048 + kbA);
#pragma unroll
            for (int p = 0; p < 2; p++)
                ldsm_x4(bf[2*p][0], bf[2*p][1], bf[2*p+1][0], bf[2*p+1][1],
                        b_base + p * 2048 + kbB);
#pragma unroll
            for (int mt = 0; mt < 2; mt++)
#pragma unroll
                for (int nt = 0; nt < 4; nt++)
                    MMA_F16(acc[mt][nt], af[mt], bf[nt][0], bf[nt][1]);
        }

        if (c + 2 < N_CHUNK) ISSUE_CHUNK2(c + 2, (c + 2) % 3);
        CP_COMMIT();
    }
#undef ISSUE_CHUNK2

#pragma unroll
    for (int mt = 0; mt < 2; mt++) {
#pragma unroll
        for (int nt = 0; nt < 4; nt++) {
            int row = bm + wm + mt * 16 + g;
            int col = bn + wn + nt * 8 + tig * 2;
            *(float2*)&C[(size_t)row * N + col] =
                make_float2(acc[mt][nt][0], acc[mt][nt][1]);
            *(float2*)&C[(size_t)(row + 8) * N + col] =
                make_float2(acc[mt][nt][2], acc[mt][nt][3]);
        }
    }
}

// ---------------------------------------------------------------------------
// Gather attention: 512 threads = 16 warps = 16 consecutive t, one h.
// k/v/(1+se) staged in fp16 (halved smem traffic); all math fp32.
// ---------------------------------------------------------------------------
__global__ __launch_bounds__(512)
void attn_kernel(const float* __restrict__ pos_bias,    // [J, H]
                 const float* __restrict__ scale_embed, // [J, 64]
                 const float* __restrict__ if_gain)     // [H]
{
    __shared__ __align__(16) __half s_k[56 * 64];
    __shared__ __align__(16) __half s_v[56 * 64];
    __shared__ __align__(16) __half s_se[J_DIM * 64];
    __shared__ float s_pb[J_DIM];

    const int tid  = threadIdx.x;
    const int lane = tid & 31;
    const int warp = tid >> 5;
    const int t0   = (blockIdx.x * 16) & (T_DIM - 1);
    const int h    = blockIdx.x >> 7;
    const int half = lane >> 4;
    const int sl   = lane & 15;

    for (int i = tid; i < 56 * 16; i += 512) {
        int r = i >> 4, d = (i & 15) * 4;
        int gr = t0 - 40 + r;
        if (gr < 0) gr = 0;
        const float* kp = g_qkv + (size_t)gr * QKV_N + C_DIM + h * 64 + d;
        *(uint2*)&s_k[r * 64 + d] = f4_to_h4(*(const float4*)kp);
        *(uint2*)&s_v[r * 64 + d] = f4_to_h4(*(const float4*)(kp + C_DIM));
    }
    for (int i = tid; i < J_DIM * 16; i += 512) {
        float4 v = ((const float4*)scale_embed)[i];
        ((uint2*)s_se)[i] = f4_to_h4(
            make_float4(1.f + v.x, 1.f + v.y, 1.f + v.z, 1.f + v.w));
    }
    if (tid < J_DIM) s_pb[tid] = pos_bias[tid * H_DIM + h];
    __syncthreads();

    const int t = t0 + warp;
    const float4 q = *(const float4*)(g_qkv + (size_t)t * QKV_N + h * 64 + sl * 4);

    float sc0 = -1e30f, sc1 = -1e30f;
#pragma unroll
    for (int jj = 0; jj < 22; jj++) {
        const int j = 2 * jj + half;
        const int idx = t - c_deltas[j];
        float4 kk;
        if (j < 41) {
            int r = t - t0 + 40 - j;
            kk = h4_to_f4(*(const uint2*)&s_k[r * 64 + sl * 4]);
        } else {
            int ic = idx < 0 ? 0 : idx;
            kk = *(const float4*)(g_qkv + (size_t)ic * QKV_N + C_DIM + h * 64 + sl * 4);
        }
        const float4 se = h4_to_f4(*(const uint2*)&s_se[j * 64 + sl * 4]);
        float p = q.x * kk.x * se.x + q.y * kk.y * se.y
                + q.z * kk.z * se.z + q.w * kk.w * se.w;
        p += __shfl_xor_sync(0xffffffffu, p, 8);
        p += __shfl_xor_sync(0xffffffffu, p, 4);
        p += __shfl_xor_sync(0xffffffffu, p, 2);
        p += __shfl_xor_sync(0xffffffffu, p, 1);
        float sv = (idx >= 0) ? fmaf(p, 0.125f, s_pb[j]) : -1e30f;
        if (jj < 16) { if (sl == jj) sc0 = sv; }
        else         { if (sl == jj - 16) sc1 = sv; }
    }

    float mm = fmaxf(sc0, sc1);
#pragma unroll
    for (int o = 16; o; o >>= 1) mm = fmaxf(mm, __shfl_xor_sync(0xffffffffu, mm, o));
    const float e0 = __expf(sc0 - mm);
    const float e1 = (sl < 6) ? __expf(sc1 - mm) : 0.0f;
    float ls = e0 + e1;
#pragma unroll
    for (int o = 16; o; o >>= 1) ls += __shfl_xor_sync(0xffffffffu, ls, o);

    float4 acc = make_float4(0.f, 0.f, 0.f, 0.f);
#pragma unroll
    for (int jj = 0; jj < 22; jj++) {
        const int j = 2 * jj + half;
        const float val = (jj < 16) ? e0 : e1;
        const float ej = __shfl_sync(0xffffffffu, val, (jj & 15) + (half << 4));
        float4 vv;
        if (j < 41) {
            int r = t - t0 + 40 - j;
            vv = h4_to_f4(*(const uint2*)&s_v[r * 64 + sl * 4]);
        } else {
            int ic = t - c_deltas[j];
            if (ic < 0) ic = 0;
            vv = *(const float4*)(g_qkv + (size_t)ic * QKV_N + 2 * C_DIM + h * 64 + sl * 4);
        }
        acc.x = fmaf(ej, vv.x, acc.x);
        acc.y = fmaf(ej, vv.y, acc.y);
        acc.z = fmaf(ej, vv.z, acc.z);
        acc.w = fmaf(ej, vv.w, acc.w);
    }
    acc.x += __shfl_xor_sync(0xffffffffu, acc.x, 16);
    acc.y += __shfl_xor_sync(0xffffffffu, acc.y, 16);
    acc.z += __shfl_xor_sync(0xffffffffu, acc.z, 16);
    acc.w += __shfl_xor_sync(0xffffffffu, acc.w, 16);

    if (half == 0) {
        const float gn = if_gain[h] / ls;
        *(uint2*)&g_attn[(size_t)t * C_DIM + h * 64 + sl * 4] = f4_to_h4(
            make_float4(acc.x * gn, acc.y * gn, acc.z * gn, acc.w * gn));
    }
}

// ---------------------------------------------------------------------------
// Launch
// ---------------------------------------------------------------------------
extern "C" void kernel_launch(void* const* d_in, const int* in_sizes, int n_in,
                              void* d_out, int out_size)
{
    const float* x           = (const float*)d_in[0];
    const float* w_qkv       = (const float*)d_in[1];
    const float* w_out       = (const float*)d_in[2];
    const float* pos_bias    = (const float*)d_in[3];
    const float* scale_embed = (const float*)d_in[4];
    const float* if_gain     = (const float*)d_in[5];
    float* out = (float*)d_out;

    float *qkv_p;
    __half *attn_p, *xh, *wqt, *wot;
    cudaGetSymbolAddress((void**)&qkv_p, g_qkv);
    cudaGetSymbolAddress((void**)&attn_p, g_attn);
    cudaGetSymbolAddress((void**)&xh, g_xh);
    cudaGetSymbolAddress((void**)&wqt, g_wqt);
    cudaGetSymbolAddress((void**)&wot, g_wot);

    cudaFuncSetAttribute(h_gemm128, cudaFuncAttributeMaxDynamicSharedMemorySize,
                         GEMM_SMEM_128);
    cudaFuncSetAttribute(h_gemm64, cudaFuncAttributeMaxDynamicSharedMemorySize,
                         GEMM_SMEM_64);

    // Pre-pass: fp16 conversions
    roundh_kernel<<<(T_DIM * C_DIM / 4 + 255) / 256, 256>>>(x, xh, T_DIM * C_DIM / 4);
    tround2_kernel<<<dim3(QKV_N / 32, K_DIM / 32, 2), dim3(32, 8)>>>(
        w_qkv, wqt, w_out, wot);

    // GEMM1: qkv = x @ w_qkv   grid 24 x 16 = 384 (128x128 tiles)
    h_gemm128<<<dim3(QKV_N / 128, T_DIM / 128), 256, GEMM_SMEM_128>>>(
        xh, wqt, qkv_p, T_DIM, QKV_N);

    // Attention: 2048 blocks x 512 threads
    attn_kernel<<<T_DIM * H_DIM / 16, 512>>>(pos_bias, scale_embed, if_gain);

    // GEMM2: out = attn @ w_out   grid 8 x 32 = 256 (64x128 tiles)
    h_gemm64<<<dim3(C_DIM / 128, T_DIM / 64), 256, GEMM_SMEM_64>>>(
        attn_p, wot, out, T_DIM, C_DIM);
}

// round 13
// speedup vs baseline: 1.0255x; 1.0255x over previous
#include <cuda_runtime.h>
#include <cuda_fp16.h>
#include <cstdint>

// ---------------------------------------------------------------------------
// DSQGAttention, fp16 mma.sync path.
// qkv = x @ w_qkv ; gather-attn (44 offsets) ; out = attn @ w_out
// R13: qkv kept fp16 end-to-end (GEMM1 writes fp16; attention stages raw
//      fp16, score math uses HMUL2). Math accumulation stays fp32.
// ---------------------------------------------------------------------------

#define T_DIM 2048
#define C_DIM 1024
#define H_DIM 16
#define J_DIM 44
#define QKV_N 3072
#define K_DIM 1024

__device__ __half g_qkvh[T_DIM * QKV_N];   // fp16 qkv (GEMM1 output)
__device__ __half g_attn[T_DIM * C_DIM];   // attention out (fp16 for GEMM2)
__device__ __half g_xh[T_DIM * C_DIM];     // x, fp16
__device__ __half g_wqt[QKV_N * K_DIM];    // w_qkv^T, fp16  [n][k]
__device__ __half g_wot[C_DIM * K_DIM];    // w_out^T, fp16  [n][k]

__constant__ int c_deltas[J_DIM] = {
    0,1,2,3,4,5,6,7,8,9,10,11,12,13,14,15,16,17,18,19,
    20,21,22,23,24,25,26,27,28,29,30,31,32,33,34,35,36,37,38,39,
    40,128,384,1536
};

__device__ __forceinline__ uint32_t smem_u32(const void* p) {
    uint32_t a;
    asm("{ .reg .u64 t; cvta.to.shared.u64 t, %1; cvt.u32.u64 %0, t; }"
        : "=r"(a) : "l"(p));
    return a;
}
__device__ __forceinline__ void cp16(uint32_t s, const void* g) {
    asm volatile("cp.async.cg.shared.global [%0], [%1], 16;" :: "r"(s), "l"(g));
}
#define CP_COMMIT() asm volatile("cp.async.commit_group;" ::: "memory")
#define CP_WAIT1()  asm volatile("cp.async.wait_group 1;" ::: "memory")

__device__ __forceinline__ void ldsm_x4(uint32_t& r0, uint32_t& r1,
                                        uint32_t& r2, uint32_t& r3, uint32_t a) {
    asm volatile("ldmatrix.sync.aligned.m8n8.x4.shared.b16 {%0,%1,%2,%3}, [%4];"
                 : "=r"(r0), "=r"(r1), "=r"(r2), "=r"(r3) : "r"(a));
}
#define MMA_F16(acc, af, b0, b1)                                               \
    asm volatile(                                                              \
        "mma.sync.aligned.m16n8k16.row.col.f32.f16.f16.f32 "                   \
        "{%0,%1,%2,%3}, {%4,%5,%6,%7}, {%8,%9}, {%0,%1,%2,%3};"                \
        : "+f"((acc)[0]), "+f"((acc)[1]), "+f"((acc)[2]), "+f"((acc)[3])       \
        : "r"((af)[0]), "r"((af)[1]), "r"((af)[2]), "r"((af)[3]),              \
          "r"(b0), "r"(b1))

__device__ __forceinline__ float4 h4_to_f4(uint2 raw) {
    float2 a = __half22float2(*reinterpret_cast<__half2*>(&raw.x));
    float2 b = __half22float2(*reinterpret_cast<__half2*>(&raw.y));
    return make_float4(a.x, a.y, b.x, b.y);
}
__device__ __forceinline__ uint2 f4_to_h4(float4 v) {
    __half2 h0 = __floats2half2_rn(v.x, v.y);
    __half2 h1 = __floats2half2_rn(v.z, v.w);
    uint2 o;
    o.x = *reinterpret_cast<unsigned*>(&h0);
    o.y = *reinterpret_cast<unsigned*>(&h1);
    return o;
}

// ---------------------------------------------------------------------------
// Pre-pass: fp32 -> fp16 (same layout)
// ---------------------------------------------------------------------------
__global__ void roundh_kernel(const float* __restrict__ src,
                              __half* __restrict__ dst, int n4)
{
    int i = blockIdx.x * blockDim.x + threadIdx.x;
    if (i >= n4) return;
    ((uint2*)dst)[i] = f4_to_h4(((const float4*)src)[i]);
}

// ---------------------------------------------------------------------------
// Pre-pass: both weight transposes (z=0: w_qkv, z=1: w_out), fp16 output
// ---------------------------------------------------------------------------
__global__ void tround2_kernel(const float* __restrict__ wq, __half* __restrict__ wqt,
                               const float* __restrict__ wo, __half* __restrict__ wot)
{
    __shared__ float tile[32][33];
    const int z = blockIdx.z;
    const float* src = z ? wo : wq;
    __half* dst = z ? wot : wqt;
    const int Cc = z ? C_DIM : QKV_N;
    int bx = blockIdx.x, by = blockIdx.y;
    if (bx * 32 >= Cc) return;
    int tx = threadIdx.x, ty = threadIdx.y;
#pragma unroll
    for (int i = 0; i < 4; i++)
        tile[ty + 8*i][tx] = src[(size_t)(by*32 + ty + 8*i) * Cc + bx*32 + tx];
    __syncthreads();
#pragma unroll
    for (int i = 0; i < 4; i++)
        dst[(size_t)(bx*32 + ty + 8*i) * K_DIM + by*32 + tx] =
            __float2half_rn(tile[tx][ty + 8*i]);
}

// ---------------------------------------------------------------------------
// GEMM1: 128x128 tile, BK=64 fp16, 3-stage, 8 warps (2m x 4n), wtile 64x32.
// fp32 accum, fp16 output (qkv).
// ---------------------------------------------------------------------------
#define GEMM_SMEM_128 (3 * 32768)
#define N_CHUNK (K_DIM / 64)   // 16

__global__ __launch_bounds__(256, 2)
void h_gemm128(const __half* __restrict__ A, const __half* __restrict__ B,
               __half* __restrict__ C, int M, int N)
{
    extern __shared__ __align__(1024) char dyn_smem[];
    const uint32_t dsm = smem_u32(dyn_smem);

    const int tid  = threadIdx.x;
    const int wid  = tid >> 5;
    const int lane = tid & 31;
    const int bm = blockIdx.y * 128;
    const int bn = blockIdx.x * 128;
    const int wm = (wid & 1) * 64;
    const int wn = (wid >> 1) * 32;
    const int g   = lane >> 2;
    const int tig = lane & 3;

    const int ld_row = tid >> 1;
    const int ld_s0  = (tid & 1) * 4;
    const __half* gA = A + (size_t)(bm + ld_row) * K_DIM + ld_s0 * 8;
    const __half* gB = B + (size_t)(bn + ld_row) * K_DIM + ld_s0 * 8;
    const int ld_swz = (ld_row & 7) << 4;
    const uint32_t sA_row = ld_row * 128;

    const int swz   = (lane & 7) << 4;
    const int a_row = wm + (((lane >> 3) & 1) << 3) + (lane & 7);
    const int a_s16 = (lane >> 4) << 4;
    const int b_s16 = ((lane >> 3) & 1) << 4;
    const int b_rw  = wn + ((lane >> 4) << 3) + (lane & 7);

    float acc[4][4][4];
#pragma unroll
    for (int mt = 0; mt < 4; mt++)
#pragma unroll
        for (int nt = 0; nt < 4; nt++)
#pragma unroll
            for (int r = 0; r < 4; r++) acc[mt][nt][r] = 0.0f;

#define ISSUE_CHUNK1(c, buf)                                                   \
    do {                                                                       \
        const uint32_t sb = dsm + (buf) * 32768;                               \
        const int kf = (c) * 64;                                               \
        _Pragma("unroll")                                                      \
        for (int i = 0; i < 4; i++) {                                          \
            const int sg = ld_s0 + i;                                          \
            const uint32_t so = sA_row + ((sg * 16) ^ ld_swz);                 \
            cp16(sb + so,         gA + kf + i * 8);                            \
            cp16(sb + 16384 + so, gB + kf + i * 8);                            \
        }                                                                      \
    } while (0)

    ISSUE_CHUNK1(0, 0); CP_COMMIT();
    ISSUE_CHUNK1(1, 1); CP_COMMIT();

    for (int c = 0; c < N_CHUNK; c++) {
        CP_WAIT1();
        __syncthreads();

        const int buf = c % 3;
        const uint32_t aB = dsm + buf * 32768;
        const uint32_t bB = aB + 16384;
        const uint32_t a_base = aB + a_row * 128;
        const uint32_t b_base = bB + b_rw * 128;

#pragma unroll
        for (int kk = 0; kk < 4; kk++) {
            uint32_t af[4][4], bf[4][2];
            const uint32_t kbA = (uint32_t)((kk * 32 + a_s16) ^ swz);
            const uint32_t kbB = (uint32_t)((kk * 32 + b_s16) ^ swz);
#pragma unroll
            for (int mt = 0; mt < 4; mt++)
                ldsm_x4(af[mt][0], af[mt][1], af[mt][2], af[mt][3],
                        a_base + mt * 2048 + kbA);
#pragma unroll
            for (int p = 0; p < 2; p++)
                ldsm_x4(bf[2*p][0], bf[2*p][1], bf[2*p+1][0], bf[2*p+1][1],
                        b_base + p * 2048 + kbB);
#pragma unroll
            for (int mt = 0; mt < 4; mt++)
#pragma unroll
                for (int nt = 0; nt < 4; nt++)
                    MMA_F16(acc[mt][nt], af[mt], bf[nt][0], bf[nt][1]);
        }

        if (c + 2 < N_CHUNK) ISSUE_CHUNK1(c + 2, (c + 2) % 3);
        CP_COMMIT();
    }
#undef ISSUE_CHUNK1

#pragma unroll
    for (int mt = 0; mt < 4; mt++) {
#pragma unroll
        for (int nt = 0; nt < 4; nt++) {
            int row = bm + wm + mt * 16 + g;
            int col = bn + wn + nt * 8 + tig * 2;
            *(__half2*)&C[(size_t)row * N + col] =
                __floats2half2_rn(acc[mt][nt][0], acc[mt][nt][1]);
            *(__half2*)&C[(size_t)(row + 8) * N + col] =
                __floats2half2_rn(acc[mt][nt][2], acc[mt][nt][3]);
        }
    }
}

// ---------------------------------------------------------------------------
// GEMM2: 64x128 tile, BK=64 fp16, 3-stage, 3 CTA/SM. fp32 output. Grid 256.
// ---------------------------------------------------------------------------
#define GEMM_SMEM_64 (3 * 24576)

__global__ __launch_bounds__(256, 3)
void h_gemm64(const __half* __restrict__ A, const __half* __restrict__ B,
              float* __restrict__ C, int M, int N)
{
    extern __shared__ __align__(1024) char dyn_smem[];
    const uint32_t dsm = smem_u32(dyn_smem);

    const int tid  = threadIdx.x;
    const int wid  = tid >> 5;
    const int lane = tid & 31;
    const int bm = blockIdx.y * 64;
    const int bn = blockIdx.x * 128;
    const int wm = (wid & 1) * 32;
    const int wn = (wid >> 1) * 32;
    const int g   = lane >> 2;
    const int tig = lane & 3;

    const int a_ld_row = tid >> 2;
    const int a_ld_s0  = (tid & 3) * 2;
    const int b_ld_row = tid >> 1;
    const int b_ld_s0  = (tid & 1) * 4;

    const __half* gA = A + (size_t)(bm + a_ld_row) * K_DIM + a_ld_s0 * 8;
    const __half* gB = B + (size_t)(bn + b_ld_row) * K_DIM + b_ld_s0 * 8;
    const int a_swz = (a_ld_row & 7) << 4;
    const int b_swz = (b_ld_row & 7) << 4;
    const uint32_t a_srow = a_ld_row * 128;
    const uint32_t b_srow = b_ld_row * 128;

    const int swz   = (lane & 7) << 4;
    const int a_row = wm + (((lane >> 3) & 1) << 3) + (lane & 7);
    const int a_s16 = (lane >> 4) << 4;
    const int b_s16 = ((lane >> 3) & 1) << 4;
    const int b_rw  = wn + ((lane >> 4) << 3) + (lane & 7);

    float acc[2][4][4];
#pragma unroll
    for (int mt = 0; mt < 2; mt++)
#pragma unroll
        for (int nt = 0; nt < 4; nt++)
#pragma unroll
            for (int r = 0; r < 4; r++) acc[mt][nt][r] = 0.0f;

#define ISSUE_CHUNK2(c, buf)                                                   \
    do {                                                                       \
        const uint32_t sb = dsm + (buf) * 24576;                               \
        const int kf = (c) * 64;                                               \
        _Pragma("unroll")                                                      \
        for (int i = 0; i < 2; i++) {                                          \
            const uint32_t so = a_srow + (((a_ld_s0 + i) * 16) ^ a_swz);       \
            cp16(sb + so, gA + kf + i * 8);                                    \
        }                                                                      \
        _Pragma("unroll")                                                      \
        for (int i = 0; i < 4; i++) {                                          \
            const uint32_t so = b_srow + (((b_ld_s0 + i) * 16) ^ b_swz);       \
            cp16(sb + 8192 + so, gB + kf + i * 8);                             \
        }                                                                      \
    } while (0)

    ISSUE_CHUNK2(0, 0); CP_COMMIT();
    ISSUE_CHUNK2(1, 1); CP_COMMIT();

    for (int c = 0; c < N_CHUNK; c++) {
        CP_WAIT1();
        __syncthreads();

        const int buf = c % 3;
        const uint32_t aB = dsm + buf * 24576;
        const uint32_t bB = aB + 8192;
        const uint32_t a_base = aB + a_row * 128;
        const uint32_t b_base = bB + b_rw * 128;

#pragma unroll
        for (int kk = 0; kk < 4; kk++) {
            uint32_t af[2][4], bf[4][2];
            const uint32_t kbA = (uint32_t)((kk * 32 + a_s16) ^ swz);
            const uint32_t kbB = (uint32_t)((kk * 32 + b_s16) ^ swz);
#pragma unroll
            for (int mt = 0; mt < 2; mt++)
                ldsm_x4(af[mt][0], af[mt][1], af[mt][2], af[mt][3],
                        a_base + mt * 2048 + kbA);
#pragma unroll
            for (int p = 0; p < 2; p++)
                ldsm_x4(bf[2*p][0], bf[2*p][1], bf[2*p+1][0], bf[2*p+1][1],
                        b_base + p * 2048 + kbB);
#pragma unroll
            for (int mt = 0; mt < 2; mt++)
#pragma unroll
                for (int nt = 0; nt < 4; nt++)
                    MMA_F16(acc[mt][nt], af[mt], bf[nt][0], bf[nt][1]);
        }

        if (c + 2 < N_CHUNK) ISSUE_CHUNK2(c + 2, (c + 2) % 3);
        CP_COMMIT();
    }
#undef ISSUE_CHUNK2

#pragma unroll
    for (int mt = 0; mt < 2; mt++) {
#pragma unroll
        for (int nt = 0; nt < 4; nt++) {
            int row = bm + wm + mt * 16 + g;
            int col = bn + wn + nt * 8 + tig * 2;
            *(float2*)&C[(size_t)row * N + col] =
                make_float2(acc[mt][nt][0], acc[mt][nt][1]);
            *(float2*)&C[(size_t)(row + 8) * N + col] =
                make_float2(acc[mt][nt][2], acc[mt][nt][3]);
        }
    }
}

// ---------------------------------------------------------------------------
// Gather attention: 512 threads = 16 warps = 16 consecutive t, one h.
// qkv is fp16: staging is a raw copy; score math uses HMUL2 + fp32 accum.
// ---------------------------------------------------------------------------
__global__ __launch_bounds__(512)
void attn_kernel(const float* __restrict__ pos_bias,    // [J, H]
                 const float* __restrict__ scale_embed, // [J, 64]
                 const float* __restrict__ if_gain)     // [H]
{
    __shared__ __align__(16) __half s_k[56 * 64];
    __shared__ __align__(16) __half s_v[56 * 64];
    __shared__ __align__(16) __half s_se[J_DIM * 64];
    __shared__ float s_pb[J_DIM];

    const int tid  = threadIdx.x;
    const int lane = tid & 31;
    const int warp = tid >> 5;
    const int t0   = (blockIdx.x * 16) & (T_DIM - 1);
    const int h    = blockIdx.x >> 7;
    const int half = lane >> 4;
    const int sl   = lane & 15;

    // raw fp16 copy of dense k/v window [t0-40, t0+16)
    for (int i = tid; i < 56 * 8; i += 512) {
        int r = i >> 3, d = (i & 7) * 8;
        int gr = t0 - 40 + r;
        if (gr < 0) gr = 0;
        const __half* kp = g_qkvh + (size_t)gr * QKV_N + C_DIM + h * 64 + d;
        *(uint4*)&s_k[r * 64 + d] = *(const uint4*)kp;
        *(uint4*)&s_v[r * 64 + d] = *(const uint4*)(kp + C_DIM);
    }
    for (int i = tid; i < J_DIM * 16; i += 512) {
        float4 v = ((const float4*)scale_embed)[i];
        ((uint2*)s_se)[i] = f4_to_h4(
            make_float4(1.f + v.x, 1.f + v.y, 1.f + v.z, 1.f + v.w));
    }
    if (tid < J_DIM) s_pb[tid] = pos_bias[tid * H_DIM + h];
    __syncthreads();

    const int t = t0 + warp;
    const float4 q = h4_to_f4(
        *(const uint2*)(g_qkvh + (size_t)t * QKV_N + h * 64 + sl * 4));

    float sc0 = -1e30f, sc1 = -1e30f;
#pragma unroll
    for (int jj = 0; jj < 22; jj++) {
        const int j = 2 * jj + half;
        const int idx = t - c_deltas[j];
        uint2 kraw;
        if (j < 41) {
            int r = t - t0 + 40 - j;
            kraw = *(const uint2*)&s_k[r * 64 + sl * 4];
        } else {
            int ic = idx < 0 ? 0 : idx;
            kraw = *(const uint2*)(g_qkvh + (size_t)ic * QKV_N + C_DIM + h * 64 + sl * 4);
        }
        const uint2 seraw = *(const uint2*)&s_se[j * 64 + sl * 4];
        // k*se in half2 (one rounding), accumulate in fp32
        __half2 m0 = __hmul2(*reinterpret_cast<const __half2*>(&kraw.x),
                             *reinterpret_cast<const __half2*>(&seraw.x));
        __half2 m1 = __hmul2(*reinterpret_cast<const __half2*>(&kraw.y),
                             *reinterpret_cast<const __half2*>(&seraw.y));
        float2 f0 = __half22float2(m0);
        float2 f1 = __half22float2(m1);
        float p = q.x * f0.x + q.y * f0.y + q.z * f1.x + q.w * f1.y;
        p += __shfl_xor_sync(0xffffffffu, p, 8);
        p += __shfl_xor_sync(0xffffffffu, p, 4);
        p += __shfl_xor_sync(0xffffffffu, p, 2);
        p += __shfl_xor_sync(0xffffffffu, p, 1);
        float sv = (idx >= 0) ? fmaf(p, 0.125f, s_pb[j]) : -1e30f;
        if (jj < 16) { if (sl == jj) sc0 = sv; }
        else         { if (sl == jj - 16) sc1 = sv; }
    }

    float mm = fmaxf(sc0, sc1);
#pragma unroll
    for (int o = 16; o; o >>= 1) mm = fmaxf(mm, __shfl_xor_sync(0xffffffffu, mm, o));
    const float e0 = __expf(sc0 - mm);
    const float e1 = (sl < 6) ? __expf(sc1 - mm) : 0.0f;
    float ls = e0 + e1;
#pragma unroll
    for (int o = 16; o; o >>= 1) ls += __shfl_xor_sync(0xffffffffu, ls, o);

    float4 acc = make_float4(0.f, 0.f, 0.f, 0.f);
#pragma unroll
    for (int jj = 0; jj < 22; jj++) {
        const int j = 2 * jj + half;
        const float val = (jj < 16) ? e0 : e1;
        const float ej = __shfl_sync(0xffffffffu, val, (jj & 15) + (half << 4));
        uint2 vraw;
        if (j < 41) {
            int r = t - t0 + 40 - j;
            vraw = *(const uint2*)&s_v[r * 64 + sl * 4];
        } else {
            int ic = t - c_deltas[j];
            if (ic < 0) ic = 0;
            vraw = *(const uint2*)(g_qkvh + (size_t)ic * QKV_N + 2 * C_DIM + h * 64 + sl * 4);
        }
        const float4 vv = h4_to_f4(vraw);
        acc.x = fmaf(ej, vv.x, acc.x);
        acc.y = fmaf(ej, vv.y, acc.y);
        acc.z = fmaf(ej, vv.z, acc.z);
        acc.w = fmaf(ej, vv.w, acc.w);
    }
    acc.x += __shfl_xor_sync(0xffffffffu, acc.x, 16);
    acc.y += __shfl_xor_sync(0xffffffffu, acc.y, 16);
    acc.z += __shfl_xor_sync(0xffffffffu, acc.z, 16);
    acc.w += __shfl_xor_sync(0xffffffffu, acc.w, 16);

    if (half == 0) {
        const float gn = if_gain[h] / ls;
        *(uint2*)&g_attn[(size_t)t * C_DIM + h * 64 + sl * 4] = f4_to_h4(
            make_float4(acc.x * gn, acc.y * gn, acc.z * gn, acc.w * gn));
    }
}

// ---------------------------------------------------------------------------
// Launch
// ---------------------------------------------------------------------------
extern "C" void kernel_launch(void* const* d_in, const int* in_sizes, int n_in,
                              void* d_out, int out_size)
{
    const float* x           = (const float*)d_in[0];
    const float* w_qkv       = (const float*)d_in[1];
    const float* w_out       = (const float*)d_in[2];
    const float* pos_bias    = (const float*)d_in[3];
    const float* scale_embed = (const float*)d_in[4];
    const float* if_gain     = (const float*)d_in[5];
    float* out = (float*)d_out;

    __half *qkv_p, *attn_p, *xh, *wqt, *wot;
    cudaGetSymbolAddress((void**)&qkv_p, g_qkvh);
    cudaGetSymbolAddress((void**)&attn_p, g_attn);
    cudaGetSymbolAddress((void**)&xh, g_xh);
    cudaGetSymbolAddress((void**)&wqt, g_wqt);
    cudaGetSymbolAddress((void**)&wot, g_wot);

    cudaFuncSetAttribute(h_gemm128, cudaFuncAttributeMaxDynamicSharedMemorySize,
                         GEMM_SMEM_128);
    cudaFuncSetAttribute(h_gemm64, cudaFuncAttributeMaxDynamicSharedMemorySize,
                         GEMM_SMEM_64);

    // Pre-pass: fp16 conversions
    roundh_kernel<<<(T_DIM * C_DIM / 4 + 255) / 256, 256>>>(x, xh, T_DIM * C_DIM / 4);
    tround2_kernel<<<dim3(QKV_N / 32, K_DIM / 32, 2), dim3(32, 8)>>>(
        w_qkv, wqt, w_out, wot);

    // GEMM1: qkv = x @ w_qkv   grid 24 x 16 = 384 (128x128 tiles), fp16 out
    h_gemm128<<<dim3(QKV_N / 128, T_DIM / 128), 256, GEMM_SMEM_128>>>(
        xh, wqt, qkv_p, T_DIM, QKV_N);

    // Attention: 2048 blocks x 512 threads
    attn_kernel<<<T_DIM * H_DIM / 16, 512>>>(pos_bias, scale_embed, if_gain);

    // GEMM2: out = attn @ w_out   grid 8 x 32 = 256 (64x128 tiles)
    h_gemm64<<<dim3(C_DIM / 128, T_DIM / 64), 256, GEMM_SMEM_64>>>(
        attn_p, wot, out, T_DIM, C_DIM);
}

// round 14
// speedup vs baseline: 1.0773x; 1.0506x over previous
#include <cuda_runtime.h>
#include <cuda_fp16.h>
#include <cstdint>

// ---------------------------------------------------------------------------
// DSQGAttention, fp16 mma.sync path.
// qkv = x @ w_qkv ; gather-attn (44 offsets) ; out = attn @ w_out
// R14: attention score loop restructured — 4 groups x 8 lanes, one j per
//      group (3-shfl reduction, dense passes branch-free), weights staged in
//      smem so the v-pass uses broadcast LDS instead of shfl. Math unchanged.
// ---------------------------------------------------------------------------

#define T_DIM 2048
#define C_DIM 1024
#define H_DIM 16
#define J_DIM 44
#define QKV_N 3072
#define K_DIM 1024

__device__ __half g_qkvh[T_DIM * QKV_N];   // fp16 qkv (GEMM1 output)
__device__ __half g_attn[T_DIM * C_DIM];   // attention out (fp16 for GEMM2)
__device__ __half g_xh[T_DIM * C_DIM];     // x, fp16
__device__ __half g_wqt[QKV_N * K_DIM];    // w_qkv^T, fp16  [n][k]
__device__ __half g_wot[C_DIM * K_DIM];    // w_out^T, fp16  [n][k]

__constant__ int c_deltas[J_DIM] = {
    0,1,2,3,4,5,6,7,8,9,10,11,12,13,14,15,16,17,18,19,
    20,21,22,23,24,25,26,27,28,29,30,31,32,33,34,35,36,37,38,39,
    40,128,384,1536
};

__device__ __forceinline__ uint32_t smem_u32(const void* p) {
    uint32_t a;
    asm("{ .reg .u64 t; cvta.to.shared.u64 t, %1; cvt.u32.u64 %0, t; }"
        : "=r"(a) : "l"(p));
    return a;
}
__device__ __forceinline__ void cp16(uint32_t s, const void* g) {
    asm volatile("cp.async.cg.shared.global [%0], [%1], 16;" :: "r"(s), "l"(g));
}
#define CP_COMMIT() asm volatile("cp.async.commit_group;" ::: "memory")
#define CP_WAIT1()  asm volatile("cp.async.wait_group 1;" ::: "memory")

__device__ __forceinline__ void ldsm_x4(uint32_t& r0, uint32_t& r1,
                                        uint32_t& r2, uint32_t& r3, uint32_t a) {
    asm volatile("ldmatrix.sync.aligned.m8n8.x4.shared.b16 {%0,%1,%2,%3}, [%4];"
                 : "=r"(r0), "=r"(r1), "=r"(r2), "=r"(r3) : "r"(a));
}
#define MMA_F16(acc, af, b0, b1)                                               \
    asm volatile(                                                              \
        "mma.sync.aligned.m16n8k16.row.col.f32.f16.f16.f32 "                   \
        "{%0,%1,%2,%3}, {%4,%5,%6,%7}, {%8,%9}, {%0,%1,%2,%3};"                \
        : "+f"((acc)[0]), "+f"((acc)[1]), "+f"((acc)[2]), "+f"((acc)[3])       \
        : "r"((af)[0]), "r"((af)[1]), "r"((af)[2]), "r"((af)[3]),              \
          "r"(b0), "r"(b1))

__device__ __forceinline__ float4 h4_to_f4(uint2 raw) {
    float2 a = __half22float2(*reinterpret_cast<__half2*>(&raw.x));
    float2 b = __half22float2(*reinterpret_cast<__half2*>(&raw.y));
    return make_float4(a.x, a.y, b.x, b.y);
}
__device__ __forceinline__ uint2 f4_to_h4(float4 v) {
    __half2 h0 = __floats2half2_rn(v.x, v.y);
    __half2 h1 = __floats2half2_rn(v.z, v.w);
    uint2 o;
    o.x = *reinterpret_cast<unsigned*>(&h0);
    o.y = *reinterpret_cast<unsigned*>(&h1);
    return o;
}

// dot of 8 fp32 q-values with hmul2(k, se) pairs, fp32 accumulation
__device__ __forceinline__ float dot8(const float* qf, uint4 kraw, uint4 seraw) {
    const __half2* k2  = reinterpret_cast<const __half2*>(&kraw);
    const __half2* se2 = reinterpret_cast<const __half2*>(&seraw);
    float p = 0.0f;
#pragma unroll
    for (int i = 0; i < 4; i++) {
        float2 f = __half22float2(__hmul2(k2[i], se2[i]));
        p = fmaf(qf[2 * i], f.x, p);
        p = fmaf(qf[2 * i + 1], f.y, p);
    }
    return p;
}

// ---------------------------------------------------------------------------
// Pre-pass: fp32 -> fp16 (same layout)
// ---------------------------------------------------------------------------
__global__ void roundh_kernel(const float* __restrict__ src,
                              __half* __restrict__ dst, int n4)
{
    int i = blockIdx.x * blockDim.x + threadIdx.x;
    if (i >= n4) return;
    ((uint2*)dst)[i] = f4_to_h4(((const float4*)src)[i]);
}

// ---------------------------------------------------------------------------
// Pre-pass: both weight transposes (z=0: w_qkv, z=1: w_out), fp16 output
// ---------------------------------------------------------------------------
__global__ void tround2_kernel(const float* __restrict__ wq, __half* __restrict__ wqt,
                               const float* __restrict__ wo, __half* __restrict__ wot)
{
    __shared__ float tile[32][33];
    const int z = blockIdx.z;
    const float* src = z ? wo : wq;
    __half* dst = z ? wot : wqt;
    const int Cc = z ? C_DIM : QKV_N;
    int bx = blockIdx.x, by = blockIdx.y;
    if (bx * 32 >= Cc) return;
    int tx = threadIdx.x, ty = threadIdx.y;
#pragma unroll
    for (int i = 0; i < 4; i++)
        tile[ty + 8*i][tx] = src[(size_t)(by*32 + ty + 8*i) * Cc + bx*32 + tx];
    __syncthreads();
#pragma unroll
    for (int i = 0; i < 4; i++)
        dst[(size_t)(bx*32 + ty + 8*i) * K_DIM + by*32 + tx] =
            __float2half_rn(tile[tx][ty + 8*i]);
}

// ---------------------------------------------------------------------------
// GEMM1: 128x128 tile, BK=64 fp16, 3-stage, 8 warps (2m x 4n), wtile 64x32.
// fp32 accum, fp16 output (qkv).
// ---------------------------------------------------------------------------
#define GEMM_SMEM_128 (3 * 32768)
#define N_CHUNK (K_DIM / 64)   // 16

__global__ __launch_bounds__(256, 2)
void h_gemm128(const __half* __restrict__ A, const __half* __restrict__ B,
               __half* __restrict__ C, int M, int N)
{
    extern __shared__ __align__(1024) char dyn_smem[];
    const uint32_t dsm = smem_u32(dyn_smem);

    const int tid  = threadIdx.x;
    const int wid  = tid >> 5;
    const int lane = tid & 31;
    const int bm = blockIdx.y * 128;
    const int bn = blockIdx.x * 128;
    const int wm = (wid & 1) * 64;
    const int wn = (wid >> 1) * 32;
    const int g   = lane >> 2;
    const int tig = lane & 3;

    const int ld_row = tid >> 1;
    const int ld_s0  = (tid & 1) * 4;
    const __half* gA = A + (size_t)(bm + ld_row) * K_DIM + ld_s0 * 8;
    const __half* gB = B + (size_t)(bn + ld_row) * K_DIM + ld_s0 * 8;
    const int ld_swz = (ld_row & 7) << 4;
    const uint32_t sA_row = ld_row * 128;

    const int swz   = (lane & 7) << 4;
    const int a_row = wm + (((lane >> 3) & 1) << 3) + (lane & 7);
    const int a_s16 = (lane >> 4) << 4;
    const int b_s16 = ((lane >> 3) & 1) << 4;
    const int b_rw  = wn + ((lane >> 4) << 3) + (lane & 7);

    float acc[4][4][4];
#pragma unroll
    for (int mt = 0; mt < 4; mt++)
#pragma unroll
        for (int nt = 0; nt < 4; nt++)
#pragma unroll
            for (int r = 0; r < 4; r++) acc[mt][nt][r] = 0.0f;

#define ISSUE_CHUNK1(c, buf)                                                   \
    do {                                                                       \
        const uint32_t sb = dsm + (buf) * 32768;                               \
        const int kf = (c) * 64;                                               \
        _Pragma("unroll")                                                      \
        for (int i = 0; i < 4; i++) {                                          \
            const int sg = ld_s0 + i;                                          \
            const uint32_t so = sA_row + ((sg * 16) ^ ld_swz);                 \
            cp16(sb + so,         gA + kf + i * 8);                            \
            cp16(sb + 16384 + so, gB + kf + i * 8);                            \
        }                                                                      \
    } while (0)

    ISSUE_CHUNK1(0, 0); CP_COMMIT();
    ISSUE_CHUNK1(1, 1); CP_COMMIT();

    for (int c = 0; c < N_CHUNK; c++) {
        CP_WAIT1();
        __syncthreads();

        const int buf = c % 3;
        const uint32_t aB = dsm + buf * 32768;
        const uint32_t bB = aB + 16384;
        const uint32_t a_base = aB + a_row * 128;
        const uint32_t b_base = bB + b_rw * 128;

#pragma unroll
        for (int kk = 0; kk < 4; kk++) {
            uint32_t af[4][4], bf[4][2];
            const uint32_t kbA = (uint32_t)((kk * 32 + a_s16) ^ swz);
            const uint32_t kbB = (uint32_t)((kk * 32 + b_s16) ^ swz);
#pragma unroll
            for (int mt = 0; mt < 4; mt++)
                ldsm_x4(af[mt][0], af[mt][1], af[mt][2], af[mt][3],
                        a_base + mt * 2048 + kbA);
#pragma unroll
            for (int p = 0; p < 2; p++)
                ldsm_x4(bf[2*p][0], bf[2*p][1], bf[2*p+1][0], bf[2*p+1][1],
                        b_base + p * 2048 + kbB);
#pragma unroll
            for (int mt = 0; mt < 4; mt++)
#pragma unroll
                for (int nt = 0; nt < 4; nt++)
                    MMA_F16(acc[mt][nt], af[mt], bf[nt][0], bf[nt][1]);
        }

        if (c + 2 < N_CHUNK) ISSUE_CHUNK1(c + 2, (c + 2) % 3);
        CP_COMMIT();
    }
#undef ISSUE_CHUNK1

#pragma unroll
    for (int mt = 0; mt < 4; mt++) {
#pragma unroll
        for (int nt = 0; nt < 4; nt++) {
            int row = bm + wm + mt * 16 + g;
            int col = bn + wn + nt * 8 + tig * 2;
            *(__half2*)&C[(size_t)row * N + col] =
                __floats2half2_rn(acc[mt][nt][0], acc[mt][nt][1]);
            *(__half2*)&C[(size_t)(row + 8) * N + col] =
                __floats2half2_rn(acc[mt][nt][2], acc[mt][nt][3]);
        }
    }
}

// ---------------------------------------------------------------------------
// GEMM2: 64x128 tile, BK=64 fp16, 3-stage, 3 CTA/SM. fp32 output. Grid 256.
// ---------------------------------------------------------------------------
#define GEMM_SMEM_64 (3 * 24576)

__global__ __launch_bounds__(256, 3)
void h_gemm64(const __half* __restrict__ A, const __half* __restrict__ B,
              float* __restrict__ C, int M, int N)
{
    extern __shared__ __align__(1024) char dyn_smem[];
    const uint32_t dsm = smem_u32(dyn_smem);

    const int tid  = threadIdx.x;
    const int wid  = tid >> 5;
    const int lane = tid & 31;
    const int bm = blockIdx.y * 64;
    const int bn = blockIdx.x * 128;
    const int wm = (wid & 1) * 32;
    const int wn = (wid >> 1) * 32;
    const int g   = lane >> 2;
    const int tig = lane & 3;

    const int a_ld_row = tid >> 2;
    const int a_ld_s0  = (tid & 3) * 2;
    const int b_ld_row = tid >> 1;
    const int b_ld_s0  = (tid & 1) * 4;

    const __half* gA = A + (size_t)(bm + a_ld_row) * K_DIM + a_ld_s0 * 8;
    const __half* gB = B + (size_t)(bn + b_ld_row) * K_DIM + b_ld_s0 * 8;
    const int a_swz = (a_ld_row & 7) << 4;
    const int b_swz = (b_ld_row & 7) << 4;
    const uint32_t a_srow = a_ld_row * 128;
    const uint32_t b_srow = b_ld_row * 128;

    const int swz   = (lane & 7) << 4;
    const int a_row = wm + (((lane >> 3) & 1) << 3) + (lane & 7);
    const int a_s16 = (lane >> 4) << 4;
    const int b_s16 = ((lane >> 3) & 1) << 4;
    const int b_rw  = wn + ((lane >> 4) << 3) + (lane & 7);

    float acc[2][4][4];
#pragma unroll
    for (int mt = 0; mt < 2; mt++)
#pragma unroll
        for (int nt = 0; nt < 4; nt++)
#pragma unroll
            for (int r = 0; r < 4; r++) acc[mt][nt][r] = 0.0f;

#define ISSUE_CHUNK2(c, buf)                                                   \
    do {                                                                       \
        const uint32_t sb = dsm + (buf) * 24576;                               \
        const int kf = (c) * 64;                                               \
        _Pragma("unroll")                                                      \
        for (int i = 0; i < 2; i++) {                                          \
            const uint32_t so = a_srow + (((a_ld_s0 + i) * 16) ^ a_swz);       \
            cp16(sb + so, gA + kf + i * 8);                                    \
        }                                                                      \
        _Pragma("unroll")                                                      \
        for (int i = 0; i < 4; i++) {                                          \
            const uint32_t so = b_srow + (((b_ld_s0 + i) * 16) ^ b_swz);       \
            cp16(sb + 8192 + so, gB + kf + i * 8);                             \
        }                                                                      \
    } while (0)

    ISSUE_CHUNK2(0, 0); CP_COMMIT();
    ISSUE_CHUNK2(1, 1); CP_COMMIT();

    for (int c = 0; c < N_CHUNK; c++) {
        CP_WAIT1();
        __syncthreads();

        const int buf = c % 3;
        const uint32_t aB = dsm + buf * 24576;
        const uint32_t bB = aB + 8192;
        const uint32_t a_base = aB + a_row * 128;
        const uint32_t b_base = bB + b_rw * 128;

#pragma unroll
        for (int kk = 0; kk < 4; kk++) {
            uint32_t af[2][4], bf[4][2];
            const uint32_t kbA = (uint32_t)((kk * 32 + a_s16) ^ swz);
            const uint32_t kbB = (uint32_t)((kk * 32 + b_s16) ^ swz);
#pragma unroll
            for (int mt = 0; mt < 2; mt++)
                ldsm_x4(af[mt][0], af[mt][1], af[mt][2], af[mt][3],
                        a_base + mt * 2048 + kbA);
#pragma unroll
            for (int p = 0; p < 2; p++)
                ldsm_x4(bf[2*p][0], bf[2*p][1], bf[2*p+1][0], bf[2*p+1][1],
                        b_base + p * 2048 + kbB);
#pragma unroll
            for (int mt = 0; mt < 2; mt++)
#pragma unroll
                for (int nt = 0; nt < 4; nt++)
                    MMA_F16(acc[mt][nt], af[mt], bf[nt][0], bf[nt][1]);
        }

        if (c + 2 < N_CHUNK) ISSUE_CHUNK2(c + 2, (c + 2) % 3);
        CP_COMMIT();
    }
#undef ISSUE_CHUNK2

#pragma unroll
    for (int mt = 0; mt < 2; mt++) {
#pragma unroll
        for (int nt = 0; nt < 4; nt++) {
            int row = bm + wm + mt * 16 + g;
            int col = bn + wn + nt * 8 + tig * 2;
            *(float2*)&C[(size_t)row * N + col] =
                make_float2(acc[mt][nt][0], acc[mt][nt][1]);
            *(float2*)&C[(size_t)(row + 8) * N + col] =
                make_float2(acc[mt][nt][2], acc[mt][nt][3]);
        }
    }
}

// ---------------------------------------------------------------------------
// Gather attention: 512 threads = 16 warps = 16 consecutive t, one h.
// Score: 4 groups x 8 lanes, 1 j per group, uint4 loads, 3-shfl reduction,
// scores/weights staged in smem (no broadcast shuffles). Math fp32.
// ---------------------------------------------------------------------------
__global__ __launch_bounds__(512)
void attn_kernel(const float* __restrict__ pos_bias,    // [J, H]
                 const float* __restrict__ scale_embed, // [J, 64]
                 const float* __restrict__ if_gain)     // [H]
{
    __shared__ __align__(16) __half s_k[56 * 64];
    __shared__ __align__(16) __half s_v[56 * 64];
    __shared__ __align__(16) __half s_se[J_DIM * 64];
    __shared__ float s_pb[J_DIM];
    __shared__ float s_w[16 * 48];   // per-warp scores -> weights

    const int tid  = threadIdx.x;
    const int lane = tid & 31;
    const int warp = tid >> 5;
    const int t0   = (blockIdx.x * 16) & (T_DIM - 1);
    const int h    = blockIdx.x >> 7;

    // raw fp16 copy of dense k/v window [t0-40, t0+16)
    for (int i = tid; i < 56 * 8; i += 512) {
        int r = i >> 3, d = (i & 7) * 8;
        int gr = t0 - 40 + r;
        if (gr < 0) gr = 0;
        const __half* kp = g_qkvh + (size_t)gr * QKV_N + C_DIM + h * 64 + d;
        *(uint4*)&s_k[r * 64 + d] = *(const uint4*)kp;
        *(uint4*)&s_v[r * 64 + d] = *(const uint4*)(kp + C_DIM);
    }
    for (int i = tid; i < J_DIM * 16; i += 512) {
        float4 v = ((const float4*)scale_embed)[i];
        ((uint2*)s_se)[i] = f4_to_h4(
            make_float4(1.f + v.x, 1.f + v.y, 1.f + v.z, 1.f + v.w));
    }
    if (tid < J_DIM) s_pb[tid] = pos_bias[tid * H_DIM + h];
    __syncthreads();

    const int t = t0 + warp;
    const int group = lane >> 3;     // 0..3 (contiguous lane octets)
    const int sl8   = lane & 7;      // 8 dims (16B) per lane

    // q: 8 fp32 values per lane
    float qf[8];
    {
        uint4 qraw = *(const uint4*)(g_qkvh + (size_t)t * QKV_N + h * 64 + sl8 * 8);
        const __half2* q2 = reinterpret_cast<const __half2*>(&qraw);
#pragma unroll
        for (int i = 0; i < 4; i++) {
            float2 f = __half22float2(q2[i]);
            qf[2 * i] = f.x;
            qf[2 * i + 1] = f.y;
        }
    }

    float* wrow = &s_w[warp * 48];

    // passes 0..9: j = 4p+group <= 39, always dense
#pragma unroll
    for (int p = 0; p < 10; p++) {
        const int j = p * 4 + group;
        const int r = t - t0 + 40 - j;
        uint4 kraw  = *(const uint4*)&s_k[r * 64 + sl8 * 8];
        uint4 seraw = *(const uint4*)&s_se[j * 64 + sl8 * 8];
        float pv = dot8(qf, kraw, seraw);
        pv += __shfl_xor_sync(0xffffffffu, pv, 4);
        pv += __shfl_xor_sync(0xffffffffu, pv, 2);
        pv += __shfl_xor_sync(0xffffffffu, pv, 1);
        float sv = (t - j >= 0) ? fmaf(pv, 0.125f, s_pb[j]) : -1e30f;
        if (sl8 == 0) wrow[j] = sv;
    }
    // pass 10: j = 40..43 (group 0 dense, groups 1-3 sparse)
    {
        const int j = 40 + group;
        const int idx = t - c_deltas[j];
        uint4 kraw;
        if (group == 0) {
            kraw = *(const uint4*)&s_k[(t - t0) * 64 + sl8 * 8];
        } else {
            int ic = idx < 0 ? 0 : idx;
            kraw = *(const uint4*)(g_qkvh + (size_t)ic * QKV_N + C_DIM + h * 64 + sl8 * 8);
        }
        uint4 seraw = *(const uint4*)&s_se[j * 64 + sl8 * 8];
        float pv = dot8(qf, kraw, seraw);
        pv += __shfl_xor_sync(0xffffffffu, pv, 4);
        pv += __shfl_xor_sync(0xffffffffu, pv, 2);
        pv += __shfl_xor_sync(0xffffffffu, pv, 1);
        float sv = (idx >= 0) ? fmaf(pv, 0.125f, s_pb[j]) : -1e30f;
        if (sl8 == 0) wrow[j] = sv;
    }
    __syncwarp();

    // batched softmax over 44 scores (one per lane + 12 extras)
    float sc0 = wrow[lane];
    float sc1 = (lane < 12) ? wrow[32 + lane] : -1e30f;
    float mm = fmaxf(sc0, sc1);
#pragma unroll
    for (int o = 16; o; o >>= 1) mm = fmaxf(mm, __shfl_xor_sync(0xffffffffu, mm, o));
    const float e0 = __expf(sc0 - mm);
    const float e1 = (lane < 12) ? __expf(sc1 - mm) : 0.0f;
    float ls = e0 + e1;
#pragma unroll
    for (int o = 16; o; o >>= 1) ls += __shfl_xor_sync(0xffffffffu, ls, o);
    wrow[lane] = e0;
    if (lane < 12) wrow[32 + lane] = e1;
    __syncwarp();

    // v pass: 2 halves x 16 lanes x 4 dims; e_j from smem broadcast
    const int half = lane >> 4;
    const int sl   = lane & 15;
    float4 acc = make_float4(0.f, 0.f, 0.f, 0.f);
#pragma unroll
    for (int jj = 0; jj < 22; jj++) {
        const int j = 2 * jj + half;
        const float ej = wrow[j];
        uint2 vraw;
        if (j < 41) {
            int r = t - t0 + 40 - j;
            vraw = *(const uint2*)&s_v[r * 64 + sl * 4];
        } else {
            int ic = t - c_deltas[j];
            if (ic < 0) ic = 0;
            vraw = *(const uint2*)(g_qkvh + (size_t)ic * QKV_N + 2 * C_DIM + h * 64 + sl * 4);
        }
        const float4 vv = h4_to_f4(vraw);
        acc.x = fmaf(ej, vv.x, acc.x);
        acc.y = fmaf(ej, vv.y, acc.y);
        acc.z = fmaf(ej, vv.z, acc.z);
        acc.w = fmaf(ej, vv.w, acc.w);
    }
    acc.x += __shfl_xor_sync(0xffffffffu, acc.x, 16);
    acc.y += __shfl_xor_sync(0xffffffffu, acc.y, 16);
    acc.z += __shfl_xor_sync(0xffffffffu, acc.z, 16);
    acc.w += __shfl_xor_sync(0xffffffffu, acc.w, 16);

    if (half == 0) {
        const float gn = if_gain[h] / ls;
        *(uint2*)&g_attn[(size_t)t * C_DIM + h * 64 + sl * 4] = f4_to_h4(
            make_float4(acc.x * gn, acc.y * gn, acc.z * gn, acc.w * gn));
    }
}

// ---------------------------------------------------------------------------
// Launch
// ---------------------------------------------------------------------------
extern "C" void kernel_launch(void* const* d_in, const int* in_sizes, int n_in,
                              void* d_out, int out_size)
{
    const float* x           = (const float*)d_in[0];
    const float* w_qkv       = (const float*)d_in[1];
    const float* w_out       = (const float*)d_in[2];
    const float* pos_bias    = (const float*)d_in[3];
    const float* scale_embed = (const float*)d_in[4];
    const float* if_gain     = (const float*)d_in[5];
    float* out = (float*)d_out;

    __half *qkv_p, *attn_p, *xh, *wqt, *wot;
    cudaGetSymbolAddress((void**)&qkv_p, g_qkvh);
    cudaGetSymbolAddress((void**)&attn_p, g_attn);
    cudaGetSymbolAddress((void**)&xh, g_xh);
    cudaGetSymbolAddress((void**)&wqt, g_wqt);
    cudaGetSymbolAddress((void**)&wot, g_wot);

    cudaFuncSetAttribute(h_gemm128, cudaFuncAttributeMaxDynamicSharedMemorySize,
                         GEMM_SMEM_128);
    cudaFuncSetAttribute(h_gemm64, cudaFuncAttributeMaxDynamicSharedMemorySize,
                         GEMM_SMEM_64);

    // Pre-pass: fp16 conversions
    roundh_kernel<<<(T_DIM * C_DIM / 4 + 255) / 256, 256>>>(x, xh, T_DIM * C_DIM / 4);
    tround2_kernel<<<dim3(QKV_N / 32, K_DIM / 32, 2), dim3(32, 8)>>>(
        w_qkv, wqt, w_out, wot);

    // GEMM1: qkv = x @ w_qkv   grid 24 x 16 = 384 (128x128 tiles), fp16 out
    h_gemm128<<<dim3(QKV_N / 128, T_DIM / 128), 256, GEMM_SMEM_128>>>(
        xh, wqt, qkv_p, T_DIM, QKV_N);

    // Attention: 2048 blocks x 512 threads
    attn_kernel<<<T_DIM * H_DIM / 16, 512>>>(pos_bias, scale_embed, if_gain);

    // GEMM2: out = attn @ w_out   grid 8 x 32 = 256 (64x128 tiles)
    h_gemm64<<<dim3(C_DIM / 128, T_DIM / 64), 256, GEMM_SMEM_64>>>(
        attn_p, wot, out, T_DIM, C_DIM);
}